// round 17
// baseline (speedup 1.0000x reference)
#include <cuda_runtime.h>
#include <cstdint>

#define NUM_CLASSES 1000
#define FEAT_DIM    256
#define NROWS       262144
#define NBLK        256          // row chunks (one fused-scatter block each)
#define CAP         512          // bucket capacity per class (max count ~330)
#define LAB_CAP     2048         // smem label cache capacity

#define NSTAGE      2            // pipeline stages in the reduce
#define RPS         16           // rows per stage (16 KB)
#define ROW_BYTES   1024         // FEAT_DIM * 4
#define NCONS       128          // consumer threads (4 warps)

// Device-global scratch (no allocation allowed in kernel_launch).
// g_count starts zeroed (static init) and is re-zeroed by k_reduce each call,
// so graph replays always begin from a clean state.
__device__ alignas(16) int g_count[NUM_CLASSES];
__device__ int g_idx[NUM_CLASSES * CAP];     // 2 MB bucket array

// ---------------------------------------------------------------------------
// mbarrier / bulk-async / PDL helpers
// ---------------------------------------------------------------------------
__device__ __forceinline__ uint32_t s2u(const void* p) {
    return (uint32_t)__cvta_generic_to_shared(p);
}
__device__ __forceinline__ void mbar_init(uint32_t a, uint32_t cnt) {
    asm volatile("mbarrier.init.shared.b64 [%0], %1;" :: "r"(a), "r"(cnt) : "memory");
}
__device__ __forceinline__ void mbar_expect_tx(uint32_t a, uint32_t bytes) {
    asm volatile("mbarrier.arrive.expect_tx.shared.b64 _, [%0], %1;"
                 :: "r"(a), "r"(bytes) : "memory");
}
__device__ __forceinline__ void mbar_arrive(uint32_t a) {
    asm volatile("mbarrier.arrive.shared.b64 _, [%0];" :: "r"(a) : "memory");
}
__device__ __forceinline__ void mbar_wait(uint32_t a, uint32_t parity) {
    asm volatile(
        "{\n\t.reg .pred P;\n"
        "WL%=:\n\t"
        "mbarrier.try_wait.parity.acquire.cta.shared::cta.b64 P, [%0], %1;\n\t"
        "@P bra WD%=;\n\t"
        "bra WL%=;\n"
        "WD%=:\n\t}"
        :: "r"(a), "r"(parity) : "memory");
}
__device__ __forceinline__ void bulk_ld(uint32_t dst, const void* src,
                                        uint32_t bytes, uint32_t mbar) {
    asm volatile(
        "cp.async.bulk.shared::cta.global.mbarrier::complete_tx::bytes "
        "[%0], [%1], %2, [%3];"
        :: "r"(dst), "l"(src), "r"(bytes), "r"(mbar) : "memory");
}
__device__ __forceinline__ void pdl_wait() {
    asm volatile("griddepcontrol.wait;" ::: "memory");
}
__device__ __forceinline__ void pdl_trigger() {
    asm volatile("griddepcontrol.launch_dependents;" ::: "memory");
}

// ---------------------------------------------------------------------------
// Kernel 1 (fused prep): per-chunk hist -> bucket reservation -> scatter.
// 256 blocks x 1024 threads, one row per thread. (R12-R16 proven version.)
// ---------------------------------------------------------------------------
__global__ void __launch_bounds__(1024)
k_prep(const int* __restrict__ labels, int n, int rpb) {
    __shared__ int h[NUM_CLASSES];
    __shared__ int lab[LAB_CAP];
    int b = blockIdx.x;
    int t = threadIdx.x;
    int base = b * rpb;
    bool cache = (rpb <= LAB_CAP);

    for (int i = t; i < NUM_CLASSES; i += 1024) h[i] = 0;
    __syncthreads();

    // Phase A: histogram + label caching.
    for (int j = t; j < rpb; j += 1024) {
        int r = base + j;
        int c = (r < n) ? labels[r] : -1;
        if (cache) lab[j] = c;
        if (c >= 0) atomicAdd(&h[c], 1);
    }
    __syncthreads();

    // Phase B: reserve ranges; h[c] becomes this block's cursor base.
    for (int c = t; c < NUM_CLASSES; c += 1024) {
        int v = h[c];
        h[c] = (v > 0) ? atomicAdd(&g_count[c], v) : 0;
    }
    __syncthreads();

    // Phase C: scatter (labels from smem).
    for (int j = t; j < rpb; j += 1024) {
        int r = base + j;
        if (r < n) {
            int c = cache ? lab[j] : labels[r];
            int pos = atomicAdd(&h[c], 1);
            g_idx[c * CAP + pos] = r;
        }
    }
    pdl_trigger();
}

// ---------------------------------------------------------------------------
// Kernel 2: warp-specialized pipelined reduce, RPS=16 / NSTAGE=2 variant.
// 160 threads = 4 consumer warps + 1 producer warp. Halved per-class
// mbarrier round-trips vs RPS=8; in-flight bytes unchanged (6 x 32KB / SM).
// PDL prolog overlaps k_prep's tail. Resets g_count[c] for graph replays.
// ---------------------------------------------------------------------------
__global__ void __launch_bounds__(160, 6)
k_reduce(const char* __restrict__ featsB,
         const float* __restrict__ protos,
         float* __restrict__ out) {
    __shared__ float4 stage[NSTAGE][RPS * 64];          // 2 x 16KB
    __shared__ float4 part4[2][64];                     // 2KB combine buffer
    __shared__ alignas(8) unsigned long long mbar[2 * NSTAGE]; // full/empty pairs

    int c = blockIdx.x;
    int t = threadIdx.x;
    int start = c * CAP;

    // ---- PDL prolog: independent of k_prep's outputs ----
    float p0 = 0.f, p1 = 0.f;
    if (t < NCONS) {
        p0 = protos[c * FEAT_DIM + t];
        p1 = protos[c * FEAT_DIM + t + NCONS];
    }
    if (t == 0) {
        #pragma unroll
        for (int s = 0; s < NSTAGE; s++) {
            mbar_init(s2u(&mbar[2 * s]), 1);        // full: tx-completion
            mbar_init(s2u(&mbar[2 * s + 1]), 4);    // empty: 4 consumer warps
        }
    }
    __syncthreads();

    // ---- wait for k_prep to finish, then read its outputs ----
    pdl_wait();
    int cnt   = g_count[c];
    int nIter = (cnt + RPS - 1) / RPS;
    __syncthreads();
    if (t == 0) g_count[c] = 0;   // reset for next graph replay

    if (t >= NCONS) {
        // ---- producer warp ----
        int lane = t - NCONS;
        int idxReg = 0;
        int s = 0, wrap = 0;
        for (int i = 0; i < nIter; i++) {
            if ((i & 1) == 0) {           // refill 32 indices (2 iterations worth)
                int p = i * RPS + lane;
                idxReg = (p < cnt) ? g_idx[start + p] : 0;
            }
            if (wrap > 0)
                mbar_wait(s2u(&mbar[2 * s + 1]), (unsigned)((wrap - 1) & 1));
            int m = min(RPS, cnt - i * RPS);
            int row = __shfl_sync(0xffffffffu, idxReg, ((i & 1) << 4) + (lane & 15));
            if (lane == 0)
                mbar_expect_tx(s2u(&mbar[2 * s]), (uint32_t)m * ROW_BYTES);
            __syncwarp();
            if (lane < m)
                bulk_ld(s2u(&stage[s][0]) + (uint32_t)lane * ROW_BYTES,
                        featsB + (long)row * ROW_BYTES,
                        ROW_BYTES, s2u(&mbar[2 * s]));
            if (++s == NSTAGE) { s = 0; wrap++; }
        }
    } else {
        // ---- consumer warps (4 warps, 128 threads) ----
        int grp = t >> 6;     // 0..1
        int col = t & 63;
        float4 acc[8];
        #pragma unroll
        for (int k = 0; k < 8; k++) acc[k] = make_float4(0.f, 0.f, 0.f, 0.f);
        int s = 0, ph = 0;
        for (int i = 0; i < nIter; i++) {
            mbar_wait(s2u(&mbar[2 * s]), (unsigned)ph);
            int m = min(RPS, cnt - i * RPS);
            #pragma unroll
            for (int k = 0; k < 8; k++) {
                int rr = grp + 2 * k;
                if (rr < m) {
                    float4 v = stage[s][rr * 64 + col];
                    acc[k].x += v.x; acc[k].y += v.y;
                    acc[k].z += v.z; acc[k].w += v.w;
                }
            }
            __syncwarp();
            if ((t & 31) == 0) mbar_arrive(s2u(&mbar[2 * s + 1]));
            if (++s == NSTAGE) { s = 0; ph ^= 1; }
        }
        float4 a;
        a.x = ((acc[0].x + acc[1].x) + (acc[2].x + acc[3].x))
            + ((acc[4].x + acc[5].x) + (acc[6].x + acc[7].x));
        a.y = ((acc[0].y + acc[1].y) + (acc[2].y + acc[3].y))
            + ((acc[4].y + acc[5].y) + (acc[6].y + acc[7].y));
        a.z = ((acc[0].z + acc[1].z) + (acc[2].z + acc[3].z))
            + ((acc[4].z + acc[5].z) + (acc[6].z + acc[7].z));
        a.w = ((acc[0].w + acc[1].w) + (acc[2].w + acc[3].w))
            + ((acc[4].w + acc[5].w) + (acc[6].w + acc[7].w));
        part4[grp][col] = a;
    }

    __syncthreads();

    if (t < NCONS) {
        const float* part = (const float*)part4;   // part[g*256 + column]
        float inv = (cnt > 0) ? 0.1f / (float)cnt : 0.f;
        float s0 = part[0 * 256 + t] + part[1 * 256 + t];
        float s1 = part[0 * 256 + t + NCONS] + part[1 * 256 + t + NCONS];
        float r0 = (cnt > 0) ? (0.9f * p0 + s0 * inv) : p0;
        float r1 = (cnt > 0) ? (0.9f * p1 + s1 * inv) : p1;
        out[c * FEAT_DIM + t]         = r0;
        out[c * FEAT_DIM + t + NCONS] = r1;
    }
}

// ---------------------------------------------------------------------------
// Launch: k_prep, then k_reduce with programmatic dependent launch so its
// prolog overlaps k_prep's tail.
// ---------------------------------------------------------------------------
extern "C" void kernel_launch(void* const* d_in, const int* in_sizes, int n_in,
                              void* d_out, int out_size) {
    const float* features   = (const float*)d_in[0];
    const int*   labels     = (const int*)d_in[1];
    const float* prototypes = (const float*)d_in[2];
    float*       out        = (float*)d_out;

    int n   = in_sizes[1];
    int rpb = (n + NBLK - 1) / NBLK;   // rows per block-chunk (1024)

    k_prep<<<NBLK, 1024>>>(labels, n, rpb);

    cudaLaunchConfig_t cfg = {};
    cfg.gridDim  = dim3(NUM_CLASSES, 1, 1);
    cfg.blockDim = dim3(160, 1, 1);
    cfg.dynamicSmemBytes = 0;
    cudaLaunchAttribute attrs[1];
    attrs[0].id = cudaLaunchAttributeProgrammaticStreamSerialization;
    attrs[0].val.programmaticStreamSerializationAllowed = 1;
    cfg.attrs = attrs;
    cfg.numAttrs = 1;
    cudaLaunchKernelEx(&cfg, k_reduce, (const char*)features, prototypes, out);
}